// round 4
// baseline (speedup 1.0000x reference)
#include <cuda_runtime.h>
#include <cuda_bf16.h>
#include <cstdint>

#define NB 8192
#define ND 256
#define NK 8
#define NT 64
#define GRID 304          // 2 per SM on 152 SMs; 2080 tiles total
#define LOG2E_F 1.4426950408889634f
#define LN2_F   0.6931471805599453f
#define CH 32             // K chunk per pipeline stage
#define SROW 40           // padded bf16 row (80B): conflict-free ldmatrix
#define BUFB (128 * SROW * 2)

// ---------------- device scratch ----------------
__device__ __align__(16) __nv_bfloat16 g_z[NB * ND];
__device__ float g_Apart[NT * NB];
__device__ float g_Bpart[NT * NB];
__device__ float g_uPos[NB * NK];
__device__ float g_uDiag[NB];
__device__ float g_red[NB / 128];
__device__ unsigned g_negMinK, g_negMaxK, g_pvMinK, g_pvMaxK;
__device__ unsigned g_cnt;
__device__ float g_C1;

// ---------------- helpers ----------------
__device__ __forceinline__ unsigned enc(float f) {
    unsigned b = __float_as_uint(f);
    return (b & 0x80000000u) ? ~b : (b | 0x80000000u);
}
__device__ __forceinline__ float dec(unsigned k) {
    unsigned b = (k & 0x80000000u) ? (k ^ 0x80000000u) : ~k;
    return __uint_as_float(b);
}
__device__ __forceinline__ float ex2(float x) {
    float y; asm("ex2.approx.ftz.f32 %0, %1;" : "=f"(y) : "f"(x)); return y;
}
__device__ __forceinline__ void mma16816(float* d, const unsigned* a, const unsigned* b) {
    asm volatile(
        "mma.sync.aligned.m16n8k16.row.col.f32.bf16.bf16.f32 "
        "{%0,%1,%2,%3}, {%4,%5,%6,%7}, {%8,%9}, {%0,%1,%2,%3};\n"
        : "+f"(d[0]), "+f"(d[1]), "+f"(d[2]), "+f"(d[3])
        : "r"(a[0]), "r"(a[1]), "r"(a[2]), "r"(a[3]), "r"(b[0]), "r"(b[1]));
}
__device__ __forceinline__ void ldsm4(unsigned& r0, unsigned& r1, unsigned& r2, unsigned& r3,
                                      unsigned addr) {
    asm volatile("ldmatrix.sync.aligned.m8n8.x4.shared.b16 {%0,%1,%2,%3}, [%4];\n"
                 : "=r"(r0), "=r"(r1), "=r"(r2), "=r"(r3) : "r"(addr));
}
__device__ __forceinline__ void cpasync16(unsigned daddr, const void* src) {
    asm volatile("cp.async.cg.shared.global [%0], [%1], 16;\n" :: "r"(daddr), "l"(src));
}
__device__ __forceinline__ void cpcommit() { asm volatile("cp.async.commit_group;\n"); }
template <int N> __device__ __forceinline__ void cpwait() {
    asm volatile("cp.async.wait_group %0;\n" :: "n"(N));
}

// ---------------- kernel 0: scalars + atomic resets ----------------
__global__ void k_init(const float* __restrict__ temperature) {
    float t = temperature[0];
    float sp = (t > 20.f) ? t : log1pf(expf(t));
    g_C1 = LOG2E_F / sp;
    g_negMinK = 0xFFFFFFFFu; g_negMaxK = 0u;
    g_pvMinK  = 0xFFFFFFFFu; g_pvMaxK  = 0u;
    g_cnt = 0u;
}

// ---------------- kernel 1: L2-normalize rows (all blocks) + pv min/max (blocks<64) ----------------
__global__ void k_pre(const float* __restrict__ emb, const float* __restrict__ pv) {
    int row  = blockIdx.x * 8 + (threadIdx.x >> 5);
    int lane = threadIdx.x & 31;
    const float4* src = (const float4*)(emb + (size_t)row * ND);
    float4 v0 = src[lane * 2], v1 = src[lane * 2 + 1];
    float ss = v0.x*v0.x + v0.y*v0.y + v0.z*v0.z + v0.w*v0.w
             + v1.x*v1.x + v1.y*v1.y + v1.z*v1.z + v1.w*v1.w;
    #pragma unroll
    for (int off = 16; off; off >>= 1) ss += __shfl_xor_sync(0xffffffffu, ss, off);
    float inv = 1.f / fmaxf(sqrtf(ss), 1e-12f);
    __nv_bfloat162 o[4];
    o[0] = __floats2bfloat162_rn(v0.x*inv, v0.y*inv);
    o[1] = __floats2bfloat162_rn(v0.z*inv, v0.w*inv);
    o[2] = __floats2bfloat162_rn(v1.x*inv, v1.y*inv);
    o[3] = __floats2bfloat162_rn(v1.z*inv, v1.w*inv);
    *(uint4*)(g_z + (size_t)row * ND + lane * 8) = *(const uint4*)o;

    if (blockIdx.x < 64) {
        int i0 = (blockIdx.x * 256 + threadIdx.x) * 4;
        float4 v = *(const float4*)(pv + i0);
        float mn = fminf(fminf(v.x, v.y), fminf(v.z, v.w));
        float mx = fmaxf(fmaxf(v.x, v.y), fmaxf(v.z, v.w));
        #pragma unroll
        for (int off = 16; off; off >>= 1) {
            mn = fminf(mn, __shfl_xor_sync(0xffffffffu, mn, off));
            mx = fmaxf(mx, __shfl_xor_sync(0xffffffffu, mx, off));
        }
        __shared__ float smn[8], smx[8];
        int w = threadIdx.x >> 5;
        if (lane == 0) { smn[w] = mn; smx[w] = mx; }
        __syncthreads();
        if (threadIdx.x == 0) {
            float a = smn[0], b = smx[0];
            #pragma unroll
            for (int i = 1; i < 8; i++) { a = fminf(a, smn[i]); b = fmaxf(b, smx[i]); }
            atomicMin(&g_pvMinK, enc(a));
            atomicMax(&g_pvMaxK, enc(b));
        }
    }
}

// ---------------- kernel 2: persistent symmetric GEMM + exp-sum epilogue ----------------
// 2080 upper-triangular tiles spread over 304 persistent blocks; continuous
// cp.async chunk pipeline across tile boundaries (epilogue hides next tile's loads).
__global__ __launch_bounds__(256, 2) void k_main() {
    __shared__ __align__(16) __nv_bfloat16 sA[2][128][SROW];
    __shared__ __align__(16) __nv_bfloat16 sB[2][128][SROW];
    __shared__ float sRowA[2][128], sRowB[2][128];
    __shared__ float sColA[4][128], sColB[4][128];
    __shared__ float sMin[8], sMax[8];

    const int tid  = threadIdx.x;
    const int w    = tid >> 5, lane = tid & 31;
    const int wr   = w >> 1,   wc   = w & 1;              // warp grid 4x2, warp tile 32x64
    const int g    = lane >> 2, c   = lane & 3;

    // tile range for this block
    const int b = blockIdx.x;
    const int start = b * 6 + (b < 256 ? b : 256);
    const int cnt   = 6 + (b < 256 ? 1 : 0);
    int rt = 0, rem = start;
    while (rem >= NT - rt) { rem -= NT - rt; rt++; }
    int ct = rt + rem;

    // ldmatrix lane addressing
    unsigned aAddr[2], bAddr[4];
    {
        int rowA = wr * 32 + (lane & 15);
        int colA = (lane >> 4) * 8;
        aAddr[0] = (unsigned)__cvta_generic_to_shared(&sA[0][rowA][colA]);
        aAddr[1] = aAddr[0] + 16 * SROW * 2;
        int rowB = wc * 64 + (lane & 7) + ((lane & 16) ? 8 : 0);
        int colB = ((lane >> 3) & 1) * 8;
        unsigned b0 = (unsigned)__cvta_generic_to_shared(&sB[0][rowB][colB]);
        #pragma unroll
        for (int nj = 0; nj < 4; nj++) bAddr[nj] = b0 + nj * 16 * SROW * 2;
    }

    auto issue_chunk = [&](int buf, int rowA0, int rowB0, int kc) {
        const int k0 = kc * CH;
        #pragma unroll
        for (int itr = 0; itr < 2; itr++) {
            int idx = tid + itr * 256;
            int row = idx >> 2, q = idx & 3;
            cpasync16((unsigned)__cvta_generic_to_shared(&sA[buf][row][q * 8]),
                      g_z + (size_t)(rowA0 + row) * ND + k0 + q * 8);
            cpasync16((unsigned)__cvta_generic_to_shared(&sB[buf][row][q * 8]),
                      g_z + (size_t)(rowB0 + row) * ND + k0 + q * 8);
        }
        cpcommit();
    };

    const float C1 = g_C1;
    float umin = __int_as_float(0x7f800000);
    float umax = __int_as_float(0xff800000);

    issue_chunk(0, rt * 128, ct * 128, 0);
    int buf = 0;

    for (int it = 0; it < cnt; it++) {
        int rtn = rt, ctn = ct + 1;
        if (ctn == NT) { rtn = rt + 1; ctn = rtn; }
        const bool moreTiles = (it + 1 < cnt);

        float acc[2][8][4];
        #pragma unroll
        for (int mi = 0; mi < 2; mi++)
            #pragma unroll
            for (int ni = 0; ni < 8; ni++)
                #pragma unroll
                for (int q = 0; q < 4; q++) acc[mi][ni][q] = 0.f;

        for (int kc = 0; kc < ND / CH; kc++) {
            const bool haveNext = (kc < ND / CH - 1) || moreTiles;
            if (haveNext) {
                int nr = (kc < ND / CH - 1) ? rt : rtn;
                int nc = (kc < ND / CH - 1) ? ct : ctn;
                int nk = (kc + 1) & (ND / CH - 1);
                issue_chunk(buf ^ 1, nr * 128, nc * 128, nk);
                cpwait<1>();
            } else cpwait<0>();
            __syncthreads();
            #pragma unroll
            for (int ks = 0; ks < 2; ks++) {
                const unsigned off = buf * BUFB + ks * 32;
                unsigned af[2][4], bfr[8][2];
                ldsm4(af[0][0], af[0][1], af[0][2], af[0][3], aAddr[0] + off);
                ldsm4(af[1][0], af[1][1], af[1][2], af[1][3], aAddr[1] + off);
                #pragma unroll
                for (int nj = 0; nj < 4; nj++) {
                    unsigned r0, r1, r2, r3;
                    ldsm4(r0, r1, r2, r3, bAddr[nj] + off);
                    bfr[2*nj][0] = r0; bfr[2*nj][1] = r1;
                    bfr[2*nj+1][0] = r2; bfr[2*nj+1][1] = r3;
                }
                #pragma unroll
                for (int mi = 0; mi < 2; mi++)
                    #pragma unroll
                    for (int ni = 0; ni < 8; ni++)
                        mma16816(acc[mi][ni], af[mi], bfr[ni]);
            }
            __syncthreads();
            buf ^= 1;
        }

        // ---- epilogue for tile (rt, ct) ----
        const int dtile = ct - rt;
        const bool isDiag = (dtile == 0);
        const bool band = (dtile <= 1) || (dtile == 63);
        float rA4[4] = {0,0,0,0}, rB4[4] = {0,0,0,0};
        const int rowBase = rt * 128 + wr * 32;
        const int colBase = ct * 128 + wc * 64;
        #pragma unroll
        for (int ni = 0; ni < 8; ni++) {
            #pragma unroll
            for (int q = 0; q < 2; q++) {
                float cA = 0.f, cB = 0.f;
                const int jG = colBase + ni * 8 + 2 * c + q;
                #pragma unroll
                for (int mi = 0; mi < 2; mi++)
                #pragma unroll
                for (int p = 0; p < 2; p++) {
                    const int ai = mi * 2 + p;
                    float d = acc[mi][ni][p * 2 + q];
                    float u = __fmaf_rn(d, C1, -C1);
                    float e = ex2(u);
                    float ue = u * e;
                    rA4[ai] += e;  rB4[ai] += ue;
                    cA += e;       cB += ue;
                    if (!band) {
                        umin = fminf(umin, u); umax = fmaxf(umax, u);
                    } else {
                        int iG = rowBase + mi * 16 + p * 8 + g;
                        int dd = (jG - iG) & (NB - 1);
                        if (isDiag) {
                            if (dd == 0)       g_uDiag[iG] = u;
                            else if (dd <= NK) g_uPos[iG * NK + dd - 1] = u;
                            else { umin = fminf(umin, u); umax = fmaxf(umax, u); }
                        } else {
                            if (dd <= NK)           g_uPos[iG * NK + dd - 1] = u;
                            else if (dd >= NB - NK) g_uPos[jG * NK + (NB - dd) - 1] = u;
                            umin = fminf(umin, u); umax = fmaxf(umax, u);
                        }
                    }
                }
                if (!isDiag) {
                    cA += __shfl_xor_sync(0xffffffffu, cA, 4);
                    cA += __shfl_xor_sync(0xffffffffu, cA, 8);
                    cA += __shfl_xor_sync(0xffffffffu, cA, 16);
                    cB += __shfl_xor_sync(0xffffffffu, cB, 4);
                    cB += __shfl_xor_sync(0xffffffffu, cB, 8);
                    cB += __shfl_xor_sync(0xffffffffu, cB, 16);
                    if (g == 0) {
                        int cl = wc * 64 + ni * 8 + 2 * c + q;
                        sColA[wr][cl] = cA; sColB[wr][cl] = cB;
                    }
                }
            }
        }
        #pragma unroll
        for (int ai = 0; ai < 4; ai++) {
            float a = rA4[ai], bb = rB4[ai];
            a  += __shfl_xor_sync(0xffffffffu, a, 1);  a  += __shfl_xor_sync(0xffffffffu, a, 2);
            bb += __shfl_xor_sync(0xffffffffu, bb, 1); bb += __shfl_xor_sync(0xffffffffu, bb, 2);
            if (c == 0) {
                int rloc = wr * 32 + (ai >> 1) * 16 + (ai & 1) * 8 + g;
                sRowA[wc][rloc] = a; sRowB[wc][rloc] = bb;
            }
        }
        __syncthreads();
        if (tid < 128) {
            g_Apart[ct * NB + rt * 128 + tid] = sRowA[0][tid] + sRowA[1][tid];
            g_Bpart[ct * NB + rt * 128 + tid] = sRowB[0][tid] + sRowB[1][tid];
        } else if (!isDiag) {
            int t2 = tid - 128;
            g_Apart[rt * NB + ct * 128 + t2] =
                sColA[0][t2] + sColA[1][t2] + sColA[2][t2] + sColA[3][t2];
            g_Bpart[rt * NB + ct * 128 + t2] =
                sColB[0][t2] + sColB[1][t2] + sColB[2][t2] + sColB[3][t2];
        }
        rt = rtn; ct = ctn;
    }

    // global neg min/max (once per block)
    #pragma unroll
    for (int off = 16; off; off >>= 1) {
        umin = fminf(umin, __shfl_xor_sync(0xffffffffu, umin, off));
        umax = fmaxf(umax, __shfl_xor_sync(0xffffffffu, umax, off));
    }
    __syncthreads();
    if (lane == 0) { sMin[w] = umin; sMax[w] = umax; }
    __syncthreads();
    if (tid == 0) {
        float mn = sMin[0], mx = sMax[0];
        #pragma unroll
        for (int i = 1; i < 8; i++) { mn = fminf(mn, sMin[i]); mx = fmaxf(mx, sMax[i]); }
        atomicMin(&g_negMinK, enc(mn));
        atomicMax(&g_negMaxK, enc(mx));
    }
}

// ---------------- kernel 3: log-denominator + weighted pos partials + final (ticket) ----------------
__global__ void k_fin1(const float* __restrict__ pv, float* __restrict__ out) {
    int i = blockIdx.x * 128 + threadIdx.x;
    float A = 0.f, Bp = 0.f;
    #pragma unroll 8
    for (int t = 0; t < NT; t++) {
        A  += g_Apart[t * NB + i];
        Bp += g_Bpart[t * NB + i];
    }
    float Bn   = Bp * LN2_F;
    float nmin = dec(g_negMinK) * LN2_F;
    float nmax = dec(g_negMaxK) * LN2_F;
    float uD = g_uDiag[i];
    float eD = ex2(uD);
    float u[NK];
    float sumE = eD, sumSE = uD * LN2_F * eD;
    #pragma unroll
    for (int k = 0; k < NK; k++) {
        u[k] = g_uPos[i * NK + k];
        float e = ex2(u[k]);
        sumE  += e;
        sumSE += u[k] * LN2_F * e;
    }
    float Aneg = A - sumE;
    float Bneg = Bn - sumSE;
    float ld = logf(A + (Bneg - nmin * Aneg) / (nmax - nmin + 1e-8f));

    float pvMax = dec(g_pvMaxK), pvMin = dec(g_pvMinK);
    float invPr = 1.f / ((pvMax - pvMin) + 1e-8f);
    float accv = 0.f;
    #pragma unroll
    for (int k = 0; k < NK; k++) {
        float pw = (pvMax - pv[i * NK + k]) * invPr;
        accv += (u[k] * LN2_F - ld) * pw;
    }
    #pragma unroll
    for (int off = 16; off; off >>= 1) accv += __shfl_xor_sync(0xffffffffu, accv, off);
    __shared__ float sp[4];
    __shared__ bool last;
    int wi = threadIdx.x >> 5;
    if ((threadIdx.x & 31) == 0) sp[wi] = accv;
    __syncthreads();
    if (threadIdx.x == 0) {
        g_red[blockIdx.x] = sp[0] + sp[1] + sp[2] + sp[3];
        __threadfence();
        unsigned t = atomicAdd(&g_cnt, 1u);
        last = (t == NB / 128 - 1);
    }
    __syncthreads();
    if (last && threadIdx.x < 32) {
        __threadfence();
        float v = g_red[threadIdx.x] + g_red[threadIdx.x + 32];
        #pragma unroll
        for (int off = 16; off; off >>= 1) v += __shfl_xor_sync(0xffffffffu, v, off);
        if (threadIdx.x == 0) out[0] = -v * (1.f / (NB * NK));
    }
}

// ---------------- launch ----------------
extern "C" void kernel_launch(void* const* d_in, const int* in_sizes, int n_in,
                              void* d_out, int out_size) {
    const float* emb  = (const float*)d_in[0];
    const float* pv   = (const float*)d_in[1];
    const float* temp = (const float*)d_in[2];
    float* out = (float*)d_out;
    (void)in_sizes; (void)n_in; (void)out_size;

    k_init<<<1, 1>>>(temp);
    k_pre<<<NB / 8, 256>>>(emb, pv);
    k_main<<<GRID, 256>>>();
    k_fin1<<<NB / 128, 128>>>(pv, out);
}

// round 5
// speedup vs baseline: 1.0859x; 1.0859x over previous
#include <cuda_runtime.h>
#include <cuda_bf16.h>
#include <cstdint>

#define NB 8192
#define ND 256
#define NK 8
#define NT 64
#define NTILE 2080        // 64*65/2 upper-triangular tiles
#define LOG2E_F 1.4426950408889634f
#define LN2_F   0.6931471805599453f
#define CH 32             // K chunk per pipeline stage
#define SROW 40           // padded bf16 row (80B): conflict-free ldmatrix
#define BUFM (128 * SROW * 2)    // 10240 B per matrix per stage

// dynamic smem layout (bytes): sA[3] | sB[3] | rowA | rowB | colA | colB | min | max
#define OFF_SB   (3 * BUFM)
#define OFF_ROWA (6 * BUFM)
#define OFF_ROWB (OFF_ROWA + 1024)
#define OFF_COLA (OFF_ROWB + 1024)
#define OFF_COLB (OFF_COLA + 2048)
#define OFF_MIN  (OFF_COLB + 2048)
#define OFF_MAX  (OFF_MIN + 32)
#define SMEM_TOTAL (OFF_MAX + 32)       // 67712 B

// ---------------- device scratch ----------------
__device__ __align__(16) __nv_bfloat16 g_z[NB * ND];
__device__ float g_Apart[NT * NB];
__device__ float g_Bpart[NT * NB];
__device__ float g_uPos[NB * NK];
__device__ float g_uDiag[NB];
__device__ float g_red[NB / 64];
__device__ unsigned g_negMinK, g_negMaxK, g_pvMinK, g_pvMaxK;
__device__ unsigned g_cnt;
__device__ float g_C1;

// ---------------- helpers ----------------
__device__ __forceinline__ unsigned enc(float f) {
    unsigned b = __float_as_uint(f);
    return (b & 0x80000000u) ? ~b : (b | 0x80000000u);
}
__device__ __forceinline__ float dec(unsigned k) {
    unsigned b = (k & 0x80000000u) ? (k ^ 0x80000000u) : ~k;
    return __uint_as_float(b);
}
__device__ __forceinline__ float ex2(float x) {
    float y; asm("ex2.approx.ftz.f32 %0, %1;" : "=f"(y) : "f"(x)); return y;
}
__device__ __forceinline__ void mma16816(float* d, const unsigned* a, const unsigned* b) {
    asm volatile(
        "mma.sync.aligned.m16n8k16.row.col.f32.bf16.bf16.f32 "
        "{%0,%1,%2,%3}, {%4,%5,%6,%7}, {%8,%9}, {%0,%1,%2,%3};\n"
        : "+f"(d[0]), "+f"(d[1]), "+f"(d[2]), "+f"(d[3])
        : "r"(a[0]), "r"(a[1]), "r"(a[2]), "r"(a[3]), "r"(b[0]), "r"(b[1]));
}
__device__ __forceinline__ void ldsm4(unsigned& r0, unsigned& r1, unsigned& r2, unsigned& r3,
                                      unsigned addr) {
    asm volatile("ldmatrix.sync.aligned.m8n8.x4.shared.b16 {%0,%1,%2,%3}, [%4];\n"
                 : "=r"(r0), "=r"(r1), "=r"(r2), "=r"(r3) : "r"(addr));
}
__device__ __forceinline__ void cpasync16(unsigned daddr, const void* src) {
    asm volatile("cp.async.cg.shared.global [%0], [%1], 16;\n" :: "r"(daddr), "l"(src));
}
__device__ __forceinline__ void cpcommit() { asm volatile("cp.async.commit_group;\n"); }
template <int N> __device__ __forceinline__ void cpwait() {
    asm volatile("cp.async.wait_group %0;\n" :: "n"(N));
}

// ---------------- kernel 0 ----------------
__global__ void k_init(const float* __restrict__ temperature) {
    float t = temperature[0];
    float sp = (t > 20.f) ? t : log1pf(expf(t));
    g_C1 = LOG2E_F / sp;
    g_negMinK = 0xFFFFFFFFu; g_negMaxK = 0u;
    g_pvMinK  = 0xFFFFFFFFu; g_pvMaxK  = 0u;
    g_cnt = 0u;
}

// ---------------- kernel 1: normalize + pv minmax ----------------
__global__ void k_pre(const float* __restrict__ emb, const float* __restrict__ pv) {
    int row  = blockIdx.x * 8 + (threadIdx.x >> 5);
    int lane = threadIdx.x & 31;
    const float4* src = (const float4*)(emb + (size_t)row * ND);
    float4 v0 = src[lane * 2], v1 = src[lane * 2 + 1];
    float ss = v0.x*v0.x + v0.y*v0.y + v0.z*v0.z + v0.w*v0.w
             + v1.x*v1.x + v1.y*v1.y + v1.z*v1.z + v1.w*v1.w;
    #pragma unroll
    for (int off = 16; off; off >>= 1) ss += __shfl_xor_sync(0xffffffffu, ss, off);
    float inv = 1.f / fmaxf(sqrtf(ss), 1e-12f);
    __nv_bfloat162 o[4];
    o[0] = __floats2bfloat162_rn(v0.x*inv, v0.y*inv);
    o[1] = __floats2bfloat162_rn(v0.z*inv, v0.w*inv);
    o[2] = __floats2bfloat162_rn(v1.x*inv, v1.y*inv);
    o[3] = __floats2bfloat162_rn(v1.z*inv, v1.w*inv);
    *(uint4*)(g_z + (size_t)row * ND + lane * 8) = *(const uint4*)o;

    if (blockIdx.x < 64) {
        int i0 = (blockIdx.x * 256 + threadIdx.x) * 4;
        float4 v = *(const float4*)(pv + i0);
        float mn = fminf(fminf(v.x, v.y), fminf(v.z, v.w));
        float mx = fmaxf(fmaxf(v.x, v.y), fmaxf(v.z, v.w));
        #pragma unroll
        for (int off = 16; off; off >>= 1) {
            mn = fminf(mn, __shfl_xor_sync(0xffffffffu, mn, off));
            mx = fmaxf(mx, __shfl_xor_sync(0xffffffffu, mx, off));
        }
        __shared__ float smn[8], smx[8];
        int w = threadIdx.x >> 5;
        if (lane == 0) { smn[w] = mn; smx[w] = mx; }
        __syncthreads();
        if (threadIdx.x == 0) {
            float a = smn[0], b = smx[0];
            #pragma unroll
            for (int i = 1; i < 8; i++) { a = fminf(a, smn[i]); b = fmaxf(b, smx[i]); }
            atomicMin(&g_pvMinK, enc(a));
            atomicMax(&g_pvMaxK, enc(b));
        }
    }
}

// ---------------- kernel 2: triangular GEMM + exp-sum epilogue (1 tile / block) ----------------
__global__ __launch_bounds__(256, 2) void k_main() {
    extern __shared__ __align__(16) char smem[];
    __nv_bfloat16* sABase = (__nv_bfloat16*)smem;
    __nv_bfloat16* sBBase = (__nv_bfloat16*)(smem + OFF_SB);
    float* sRowA = (float*)(smem + OFF_ROWA);
    float* sRowB = (float*)(smem + OFF_ROWB);
    float* sColA = (float*)(smem + OFF_COLA);
    float* sColB = (float*)(smem + OFF_COLB);
    float* sMin  = (float*)(smem + OFF_MIN);
    float* sMax  = (float*)(smem + OFF_MAX);

    const int tid  = threadIdx.x;
    const int w    = tid >> 5, lane = tid & 31;
    const int wr   = w >> 1,   wc   = w & 1;              // warp grid 4x2, warp tile 32x64
    const int g    = lane >> 2, c   = lane & 3;

    // decode triangular tile index (row-major upper triangle)
    int rt = 0, rem = blockIdx.x;
    while (rem >= NT - rt) { rem -= NT - rt; rt++; }
    const int ct = rt + rem;
    const int rowA0 = rt * 128, rowB0 = ct * 128;

    // ldmatrix lane addressing (stage 0; add st*BUFM per stage)
    unsigned aAddr[2], bAddr[4];
    {
        int rowA = wr * 32 + (lane & 15);
        int colA = (lane >> 4) * 8;
        aAddr[0] = (unsigned)__cvta_generic_to_shared(&sABase[rowA * SROW + colA]);
        aAddr[1] = aAddr[0] + 16 * SROW * 2;
        int rowB = wc * 64 + (lane & 7) + ((lane & 16) ? 8 : 0);
        int colB = ((lane >> 3) & 1) * 8;
        unsigned b0 = (unsigned)__cvta_generic_to_shared(&sBBase[rowB * SROW + colB]);
        #pragma unroll
        for (int nj = 0; nj < 4; nj++) bAddr[nj] = b0 + nj * 16 * SROW * 2;
    }

    auto issue_chunk = [&](int st, int kc) {
        const int k0 = kc * CH;
        __nv_bfloat16* dA = sABase + st * (BUFM / 2);
        __nv_bfloat16* dB = sBBase + st * (BUFM / 2);
        #pragma unroll
        for (int itr = 0; itr < 2; itr++) {
            int idx = tid + itr * 256;
            int row = idx >> 2, q = idx & 3;
            cpasync16((unsigned)__cvta_generic_to_shared(&dA[row * SROW + q * 8]),
                      g_z + (size_t)(rowA0 + row) * ND + k0 + q * 8);
            cpasync16((unsigned)__cvta_generic_to_shared(&dB[row * SROW + q * 8]),
                      g_z + (size_t)(rowB0 + row) * ND + k0 + q * 8);
        }
        cpcommit();
    };

    float acc[2][8][4];
    #pragma unroll
    for (int mi = 0; mi < 2; mi++)
        #pragma unroll
        for (int ni = 0; ni < 8; ni++)
            #pragma unroll
            for (int q = 0; q < 4; q++) acc[mi][ni][q] = 0.f;

    issue_chunk(0, 0);
    issue_chunk(1, 1);

    #pragma unroll
    for (int kc = 0; kc < ND / CH; kc++) {
        const int st = kc % 3;
        if (kc == ND / CH - 1) cpwait<0>(); else cpwait<1>();
        __syncthreads();                                   // single barrier per chunk
        if (kc + 2 < ND / CH) issue_chunk((kc + 2) % 3, kc + 2);
        #pragma unroll
        for (int ks = 0; ks < 2; ks++) {
            const unsigned off = st * BUFM + ks * 32;      // ks*16 cols * 2B
            unsigned af[2][4], bfr[8][2];
            ldsm4(af[0][0], af[0][1], af[0][2], af[0][3], aAddr[0] + off);
            ldsm4(af[1][0], af[1][1], af[1][2], af[1][3], aAddr[1] + off);
            #pragma unroll
            for (int nj = 0; nj < 4; nj++) {
                unsigned r0, r1, r2, r3;
                ldsm4(r0, r1, r2, r3, bAddr[nj] + off);
                bfr[2*nj][0] = r0; bfr[2*nj][1] = r1;
                bfr[2*nj+1][0] = r2; bfr[2*nj+1][1] = r3;
            }
            #pragma unroll
            for (int mi = 0; mi < 2; mi++)
                #pragma unroll
                for (int ni = 0; ni < 8; ni++)
                    mma16816(acc[mi][ni], af[mi], bfr[ni]);
        }
    }

    // ---- epilogue ----
    const float C1 = g_C1;
    const int dtile = ct - rt;
    const bool isDiag = (dtile == 0);
    const bool band = (dtile <= 1) || (dtile == 63);
    float rA4[4] = {0,0,0,0}, rB4[4] = {0,0,0,0};
    float umin = __int_as_float(0x7f800000);
    float umax = __int_as_float(0xff800000);
    const int rowBase = rt * 128 + wr * 32;
    const int colBase = ct * 128 + wc * 64;
    #pragma unroll
    for (int ni = 0; ni < 8; ni++) {
        #pragma unroll
        for (int q = 0; q < 2; q++) {
            float cA = 0.f, cB = 0.f;
            const int jG = colBase + ni * 8 + 2 * c + q;
            #pragma unroll
            for (int mi = 0; mi < 2; mi++)
            #pragma unroll
            for (int p = 0; p < 2; p++) {
                const int ai = mi * 2 + p;
                float d = acc[mi][ni][p * 2 + q];
                float u = __fmaf_rn(d, C1, -C1);
                float e = ex2(u);
                float ue = u * e;
                rA4[ai] += e;  rB4[ai] += ue;
                cA += e;       cB += ue;
                if (!band) {
                    umin = fminf(umin, u); umax = fmaxf(umax, u);
                } else {
                    int iG = rowBase + mi * 16 + p * 8 + g;
                    int dd = (jG - iG) & (NB - 1);
                    if (isDiag) {
                        if (dd == 0)       g_uDiag[iG] = u;
                        else if (dd <= NK) g_uPos[iG * NK + dd - 1] = u;
                        else { umin = fminf(umin, u); umax = fmaxf(umax, u); }
                    } else {
                        if (dd <= NK)           g_uPos[iG * NK + dd - 1] = u;
                        else if (dd >= NB - NK) g_uPos[jG * NK + (NB - dd) - 1] = u;
                        umin = fminf(umin, u); umax = fmaxf(umax, u);
                    }
                }
            }
            if (!isDiag) {
                cA += __shfl_xor_sync(0xffffffffu, cA, 4);
                cA += __shfl_xor_sync(0xffffffffu, cA, 8);
                cA += __shfl_xor_sync(0xffffffffu, cA, 16);
                cB += __shfl_xor_sync(0xffffffffu, cB, 4);
                cB += __shfl_xor_sync(0xffffffffu, cB, 8);
                cB += __shfl_xor_sync(0xffffffffu, cB, 16);
                if (g == 0) {
                    int cl = wc * 64 + ni * 8 + 2 * c + q;
                    sColA[wr * 128 + cl] = cA; sColB[wr * 128 + cl] = cB;
                }
            }
        }
    }
    #pragma unroll
    for (int ai = 0; ai < 4; ai++) {
        float a = rA4[ai], bb = rB4[ai];
        a  += __shfl_xor_sync(0xffffffffu, a, 1);  a  += __shfl_xor_sync(0xffffffffu, a, 2);
        bb += __shfl_xor_sync(0xffffffffu, bb, 1); bb += __shfl_xor_sync(0xffffffffu, bb, 2);
        if (c == 0) {
            int rloc = wr * 32 + (ai >> 1) * 16 + (ai & 1) * 8 + g;
            sRowA[wc * 128 + rloc] = a; sRowB[wc * 128 + rloc] = bb;
        }
    }
    #pragma unroll
    for (int off = 16; off; off >>= 1) {
        umin = fminf(umin, __shfl_xor_sync(0xffffffffu, umin, off));
        umax = fmaxf(umax, __shfl_xor_sync(0xffffffffu, umax, off));
    }
    if (lane == 0) { sMin[w] = umin; sMax[w] = umax; }
    __syncthreads();
    if (tid < 128) {
        g_Apart[ct * NB + rt * 128 + tid] = sRowA[tid] + sRowA[128 + tid];
        g_Bpart[ct * NB + rt * 128 + tid] = sRowB[tid] + sRowB[128 + tid];
    } else if (!isDiag) {
        int t2 = tid - 128;
        g_Apart[rt * NB + ct * 128 + t2] =
            sColA[t2] + sColA[128 + t2] + sColA[256 + t2] + sColA[384 + t2];
        g_Bpart[rt * NB + ct * 128 + t2] =
            sColB[t2] + sColB[128 + t2] + sColB[256 + t2] + sColB[384 + t2];
    }
    if (tid == 0) {
        float mn = sMin[0], mx = sMax[0];
        #pragma unroll
        for (int i = 1; i < 8; i++) { mn = fminf(mn, sMin[i]); mx = fmaxf(mx, sMax[i]); }
        atomicMin(&g_negMinK, enc(mn));
        atomicMax(&g_negMaxK, enc(mx));
    }
}

// ---------------- kernel 3: log-denominator + weighted pos partials + final (4 thr/row) ----------------
__global__ void k_fin1(const float* __restrict__ pv, float* __restrict__ out) {
    int gt = blockIdx.x * 256 + threadIdx.x;
    int row = gt >> 2, part = gt & 3;
    float A = 0.f, Bp = 0.f;
    #pragma unroll
    for (int t = part; t < NT; t += 4) {
        A  += g_Apart[t * NB + row];
        Bp += g_Bpart[t * NB + row];
    }
    A  += __shfl_xor_sync(0xffffffffu, A, 1);  A  += __shfl_xor_sync(0xffffffffu, A, 2);
    Bp += __shfl_xor_sync(0xffffffffu, Bp, 1); Bp += __shfl_xor_sync(0xffffffffu, Bp, 2);

    // positives tail split 2 k per thread
    float u0 = g_uPos[row * NK + part * 2];
    float u1 = g_uPos[row * NK + part * 2 + 1];
    float e0 = ex2(u0), e1 = ex2(u1);
    float sumE  = e0 + e1;
    float sumSE = (u0 * e0 + u1 * e1) * LN2_F;
    if (part == 0) {
        float uD = g_uDiag[row];
        float eD = ex2(uD);
        sumE += eD; sumSE += uD * LN2_F * eD;
    }
    sumE  += __shfl_xor_sync(0xffffffffu, sumE, 1);
    sumE  += __shfl_xor_sync(0xffffffffu, sumE, 2);
    sumSE += __shfl_xor_sync(0xffffffffu, sumSE, 1);
    sumSE += __shfl_xor_sync(0xffffffffu, sumSE, 2);

    float Bn   = Bp * LN2_F;
    float nmin = dec(g_negMinK) * LN2_F;
    float nmax = dec(g_negMaxK) * LN2_F;
    float Aneg = A - sumE;
    float Bneg = Bn - sumSE;
    float ld = logf(A + (Bneg - nmin * Aneg) / (nmax - nmin + 1e-8f));

    float pvMax = dec(g_pvMaxK), pvMin = dec(g_pvMinK);
    float invPr = 1.f / ((pvMax - pvMin) + 1e-8f);
    float pw0 = (pvMax - pv[row * NK + part * 2]) * invPr;
    float pw1 = (pvMax - pv[row * NK + part * 2 + 1]) * invPr;
    float accv = (u0 * LN2_F - ld) * pw0 + (u1 * LN2_F - ld) * pw1;

    #pragma unroll
    for (int off = 16; off; off >>= 1) accv += __shfl_xor_sync(0xffffffffu, accv, off);
    __shared__ float sp[8];
    __shared__ bool last;
    int wi = threadIdx.x >> 5;
    if ((threadIdx.x & 31) == 0) sp[wi] = accv;
    __syncthreads();
    if (threadIdx.x == 0) {
        float s = 0.f;
        #pragma unroll
        for (int i = 0; i < 8; i++) s += sp[i];
        g_red[blockIdx.x] = s;
        __threadfence();
        unsigned t = atomicAdd(&g_cnt, 1u);
        last = (t == NB / 64 - 1);
    }
    __syncthreads();
    if (last && threadIdx.x < 128) {
        __threadfence();
        float v = g_red[threadIdx.x];
        #pragma unroll
        for (int off = 16; off; off >>= 1) v += __shfl_xor_sync(0xffffffffu, v, off);
        if ((threadIdx.x & 31) == 0) sp[threadIdx.x >> 5] = v;
        __syncthreads();
        if (threadIdx.x == 0)
            out[0] = -(sp[0] + sp[1] + sp[2] + sp[3]) * (1.f / (NB * NK));
    }
}

// ---------------- launch ----------------
extern "C" void kernel_launch(void* const* d_in, const int* in_sizes, int n_in,
                              void* d_out, int out_size) {
    const float* emb  = (const float*)d_in[0];
    const float* pv   = (const float*)d_in[1];
    const float* temp = (const float*)d_in[2];
    float* out = (float*)d_out;
    (void)in_sizes; (void)n_in; (void)out_size;

    cudaFuncSetAttribute(k_main, cudaFuncAttributeMaxDynamicSharedMemorySize, SMEM_TOTAL);

    k_init<<<1, 1>>>(temp);
    k_pre<<<NB / 8, 256>>>(emb, pv);
    k_main<<<NTILE, 256, SMEM_TOTAL>>>();
    k_fin1<<<NB / 64, 256>>>(pv, out);
}